// round 14
// baseline (speedup 1.0000x reference)
#include <cuda_runtime.h>
#include <cuda_fp16.h>
#include <cstdint>
#include <math.h>

#define BB 4
#define NN 2048
#define DD 1024
#define HH 16
#define DHD 64
#define MTOT (BB*NN)   // 8192

// Scratch (device globals)
__device__ __half g_xh[MTOT * DD];
__device__ __half g_qh[MTOT * DD];
__device__ __half g_kh[MTOT * DD];
__device__ __half g_vh[MTOT * DD];
__device__ __half g_ch[MTOT * DD];
__device__ __half g_wh[4 * DD * DD];

__device__ __forceinline__ float fast_exp2(float x) {
    float y;
    asm("ex2.approx.ftz.f32 %0, %1;" : "=f"(y) : "f"(x));
    return y;
}
__device__ __forceinline__ uint32_t smem_u32(const void* p) {
    uint32_t a;
    asm("{ .reg .u64 t; cvta.to.shared.u64 t, %1; cvt.u32.u64 %0, t; }" : "=r"(a) : "l"(p));
    return a;
}
__device__ __forceinline__ uint32_t pack_h2(float x, float y) {
    __half2 h = __floats2half2_rn(x, y);
    return *(uint32_t*)&h;
}
__device__ __forceinline__ void ldsm_x4(uint32_t* r, uint32_t addr) {
    asm volatile("ldmatrix.sync.aligned.m8n8.x4.shared.b16 {%0,%1,%2,%3}, [%4];"
                 : "=r"(r[0]), "=r"(r[1]), "=r"(r[2]), "=r"(r[3]) : "r"(addr));
}
__device__ __forceinline__ void ldsm_x4_t(uint32_t* r, uint32_t addr) {
    asm volatile("ldmatrix.sync.aligned.m8n8.x4.trans.shared.b16 {%0,%1,%2,%3}, [%4];"
                 : "=r"(r[0]), "=r"(r[1]), "=r"(r[2]), "=r"(r[3]) : "r"(addr));
}
#define MMA_F16(c, a, b0, b1)                                                 \
    asm volatile("mma.sync.aligned.m16n8k16.row.col.f32.f16.f16.f32 "         \
                 "{%0,%1,%2,%3},{%4,%5,%6,%7},{%8,%9},{%0,%1,%2,%3};"         \
                 : "+f"((c)[0]), "+f"((c)[1]), "+f"((c)[2]), "+f"((c)[3])     \
                 : "r"((a)[0]), "r"((a)[1]), "r"((a)[2]), "r"((a)[3]),        \
                   "r"(b0), "r"(b1))
#define CP_ASYNC16(dst, src)                                                  \
    asm volatile("cp.async.cg.shared.global [%0], [%1], 16;" :: "r"(dst), "l"(src))
#define CP_COMMIT()  asm volatile("cp.async.commit_group;")
#define CP_WAIT0()   asm volatile("cp.async.wait_group 0;")
#define CP_WAIT1()   asm volatile("cp.async.wait_group 1;")
#define HONES 0x3C003C00u   /* (1.0h, 1.0h) */

// ===========================================================================
// Prep kernels
// ===========================================================================
__global__ void wprep(const float* __restrict__ W0, const float* __restrict__ W1,
                      const float* __restrict__ W2, const float* __restrict__ W3)
{
    const float* S;
    switch (blockIdx.y) {
        case 0: S = W0; break;
        case 1: S = W1; break;
        case 2: S = W2; break;
        default: S = W3; break;
    }
    int idx = blockIdx.x * 256 + threadIdx.x;
    g_wh[(size_t)blockIdx.y * DD * DD + idx] = __float2half_rn(S[idx]);
}

__global__ void xprep(const float* __restrict__ x)
{
    size_t i = ((size_t)blockIdx.x * 256 + threadIdx.x) * 4;
    float4 v = *(const float4*)(x + i);
    uint2 u;
    u.x = pack_h2(v.x, v.y);
    u.y = pack_h2(v.z, v.w);
    *(uint2*)&g_xh[i] = u;
}

// ===========================================================================
// fp16 GEMM: 128x128 CTA tile, BK=64, 8 warps, 3-stage cp.async pipeline,
// B-fragment register double-buffering inside the stage.
// ===========================================================================
#define ASTR 72
#define BSTR 136
#define ABUF (128 * ASTR)
#define BBUF (64 * BSTR)
#define SBUF (ABUF + BBUF)
#define GH_SMEM (3 * SBUF * 2)        // 107520 bytes

__device__ __forceinline__
void gemm_body(const __half* __restrict__ Ah, const __half* __restrict__ Wh,
               const float* __restrict__ bias, float* __restrict__ Cf,
               __half* __restrict__ Ch, int m0, int n0)
{
    extern __shared__ __align__(16) __half hsm[];
    const uint32_t smb = smem_u32(hsm);
    uint32_t asb[3], bsb[3];
#pragma unroll
    for (int s = 0; s < 3; s++) {
        asb[s] = smb + s * SBUF * 2;
        bsb[s] = asb[s] + ABUF * 2;
    }

    const int tid  = threadIdx.x;
    const int lane = tid & 31, wid = tid >> 5;
    const int wm = wid & 3, wn = wid >> 2;
    const int p = lane >> 2, q = lane & 3;

    auto cp_tile = [&](int k0, int s) {
#pragma unroll
        for (int i = 0; i < 4; i++) {
            const int j = tid + i * 256;
            const int row = j >> 3, c8 = j & 7;
            CP_ASYNC16(asb[s] + (row * ASTR + c8 * 8) * 2,
                       Ah + (size_t)(m0 + row) * DD + k0 + c8 * 8);
        }
#pragma unroll
        for (int i = 0; i < 4; i++) {
            const int j = tid + i * 256;
            const int row = j >> 4, cc = j & 15;
            CP_ASYNC16(bsb[s] + (row * BSTR + cc * 8) * 2,
                       Wh + (size_t)(k0 + row) * DD + n0 + cc * 8);
        }
    };

    float c[2][8][4];
#pragma unroll
    for (int mi = 0; mi < 2; mi++)
#pragma unroll
        for (int ni = 0; ni < 8; ni++)
#pragma unroll
            for (int e = 0; e < 4; e++) c[mi][ni][e] = 0.f;

    const int lrow  = lane & 15;
    const int lcolA = (lane >> 4) * 8;
    const int brow  = (lane & 7) + ((lane >> 3) & 1) * 8;
    const int bcol  = wn * 64 + ((lane >> 4) & 1) * 8;

    cp_tile(0, 0);  CP_COMMIT();
    cp_tile(64, 1); CP_COMMIT();

    uint32_t bf[2][4][4];   // double-buffered B fragments

    for (int ks = 0; ks < 16; ks++) {
        const int s = ks % 3;
        if (ks == 15) { CP_WAIT0(); } else { CP_WAIT1(); }
        __syncthreads();
        if (ks + 2 < 16) {
            cp_tile((ks + 2) * 64, (ks + 2) % 3);
            CP_COMMIT();
        }

        // preload B frags for kk=0
#pragma unroll
        for (int pr = 0; pr < 4; pr++)
            ldsm_x4_t(bf[0][pr], bsb[s] + (brow * BSTR + bcol + pr * 16) * 2);

#pragma unroll
        for (int kk = 0; kk < 4; kk++) {
            const int cur = kk & 1;
            if (kk < 3) {
#pragma unroll
                for (int pr = 0; pr < 4; pr++)
                    ldsm_x4_t(bf[cur ^ 1][pr], bsb[s] +
                              (((kk + 1) * 16 + brow) * BSTR + bcol + pr * 16) * 2);
            }
            uint32_t a[2][4];
#pragma unroll
            for (int mi = 0; mi < 2; mi++)
                ldsm_x4(a[mi], asb[s] +
                        ((wm * 32 + mi * 16 + lrow) * ASTR + kk * 16 + lcolA) * 2);
#pragma unroll
            for (int mi = 0; mi < 2; mi++)
#pragma unroll
                for (int pr = 0; pr < 4; pr++) {
                    MMA_F16(c[mi][2 * pr],     a[mi], bf[cur][pr][0], bf[cur][pr][1]);
                    MMA_F16(c[mi][2 * pr + 1], a[mi], bf[cur][pr][2], bf[cur][pr][3]);
                }
        }
    }

#pragma unroll
    for (int mi = 0; mi < 2; mi++) {
        const int r = m0 + wm * 32 + mi * 16 + p;
#pragma unroll
        for (int ni = 0; ni < 8; ni++) {
            const int col = n0 + wn * 64 + ni * 8 + 2 * q;
            if (Ch) {
                *(uint32_t*)&Ch[(size_t)r * DD + col] =
                    pack_h2(c[mi][ni][0], c[mi][ni][1]);
                *(uint32_t*)&Ch[(size_t)(r + 8) * DD + col] =
                    pack_h2(c[mi][ni][2], c[mi][ni][3]);
            } else {
                float2 v0 = make_float2(c[mi][ni][0], c[mi][ni][1]);
                float2 v1 = make_float2(c[mi][ni][2], c[mi][ni][3]);
                if (bias) {
                    float b0 = bias[col], b1 = bias[col + 1];
                    v0.x += b0; v0.y += b1;
                    v1.x += b0; v1.y += b1;
                }
                *(float2*)&Cf[(size_t)r * DD + col]       = v0;
                *(float2*)&Cf[(size_t)(r + 8) * DD + col] = v1;
            }
        }
    }
}

__global__ __launch_bounds__(256, 2)
void gemm_qkv()
{
    const int widx = blockIdx.x >> 3;
    const int n0 = (blockIdx.x & 7) * 128;
    __half* outp = (widx == 0) ? g_qh : (widx == 1) ? g_kh : g_vh;
    gemm_body(g_xh, g_wh + (size_t)widx * DD * DD, nullptr, nullptr, outp,
              blockIdx.y * 128, n0);
}

__global__ __launch_bounds__(256, 2)
void gemm_wo(const float* __restrict__ bias, float* __restrict__ out)
{
    gemm_body(g_ch, g_wh + (size_t)3 * DD * DD, bias, out, nullptr,
              blockIdx.y * 128, blockIdx.x * 128);
}

// ===========================================================================
// fp16 causal flash attention, ONE 128-row q-tile per CTA, heaviest-first.
// 256 threads (8 warps), 128-token KV tiles (2 x 64-chunk), 2-buffer
// cp.async, one barrier per 128 tokens, static softmax shift (max := 0),
// row sums via ones-mma.
// Grid (16, HH, BB): blockIdx.x = i -> q-tile t = 15 - i (heavy CTAs first
// in bid order for near-ideal wave packing).
// ===========================================================================
#define C2F 0.18033688f
#define KVTILE_B (128 * 64 * 2)       // 16384 B per K (or V) tile
#define FL_SMEM (2 * 2 * KVTILE_B)    // 65536 B

__global__ __launch_bounds__(256, 2)
void flash_h(__half* __restrict__ Oh)
{
    extern __shared__ __align__(16) __half fsm[];
    const uint32_t base = smem_u32(fsm);

    const int tid  = threadIdx.x;
    const int lane = tid & 31, w = tid >> 5;
    const int p = lane >> 2, q = lane & 3;
    const int h = blockIdx.y, b = blockIdx.z;
    const int t = 15 - blockIdx.x;          // heaviest first

    const __half* Kb = g_kh + ((size_t)b * NN) * DD + h * DHD;
    const __half* Vb = g_vh + ((size_t)b * NN) * DD + h * DHD;

    auto cp_kv = [&](int kv, int s) {
        const uint32_t kdst = base + s * 2 * KVTILE_B;
        const uint32_t vdst = kdst + KVTILE_B;
#pragma unroll
        for (int i = 0; i < 4; i++) {
            const int j = tid + i * 256;
            const int row = j >> 3, cc = j & 7;
            const uint32_t off = (row * 64 + ((cc ^ (row & 7)) * 8)) * 2;
            CP_ASYNC16(kdst + off, Kb + (size_t)(kv * 128 + row) * DD + cc * 8);
            CP_ASYNC16(vdst + off, Vb + (size_t)(kv * 128 + row) * DD + cc * 8);
        }
    };

    const int brow = (lane & 7) + ((lane >> 3) & 1) * 8;
    const int bc8  = ((lane >> 4) & 1) * 8;
    const int knr  = ((lane >> 4) & 1) * 8 + (lane & 7);
    const int kkc  = (lane >> 3) & 1;

    const int qrow = t * 128 + w * 16;
    const __half* Qb = g_qh + ((size_t)(b * NN + qrow)) * DD + h * DHD;
    const int kmax = t;

    uint32_t qf[4][4];
#pragma unroll
    for (int kb = 0; kb < 4; kb++) {
        qf[kb][0] = *(const uint32_t*)(Qb + (size_t)p * DD + kb * 16 + 2 * q);
        qf[kb][1] = *(const uint32_t*)(Qb + (size_t)(p + 8) * DD + kb * 16 + 2 * q);
        qf[kb][2] = *(const uint32_t*)(Qb + (size_t)p * DD + kb * 16 + 2 * q + 8);
        qf[kb][3] = *(const uint32_t*)(Qb + (size_t)(p + 8) * DD + kb * 16 + 2 * q + 8);
    }

    float o[8][4];
#pragma unroll
    for (int ni = 0; ni < 8; ni++)
#pragma unroll
        for (int e = 0; e < 4; e++) o[ni][e] = 0.f;
    float l0 = 0.f, l1 = 0.f;

    cp_kv(0, 0); CP_COMMIT();

    for (int kv = 0; kv <= kmax; kv++) {
        const int s = kv & 1;
        CP_WAIT0();
        __syncthreads();
        if (kv < kmax) {
            cp_kv(kv + 1, s ^ 1);
            CP_COMMIT();
        }
        const uint32_t kbase_s = base + s * 2 * KVTILE_B;
        const uint32_t vbase_s = kbase_s + KVTILE_B;

#pragma unroll
        for (int ch = 0; ch < 2; ch++) {
            const int dcol = kv * 128 + ch * 64 - t * 128;
            const int wlo = w * 16;
            if (dcol > wlo + 15) continue;
            const bool need_mask = (dcol + 63 > wlo);
            const uint32_t koff = kbase_s + ch * (64 * 64 * 2);
            const uint32_t voff = vbase_s + ch * (64 * 64 * 2);

            // ---- S = Q @ K^T ----
            float sa[8][4];
#pragma unroll
            for (int ni = 0; ni < 8; ni++)
#pragma unroll
                for (int e = 0; e < 4; e++) sa[ni][e] = 0.f;

#pragma unroll
            for (int kb = 0; kb < 4; kb++) {
#pragma unroll
                for (int nbp = 0; nbp < 4; nbp++) {
                    const int nrow = nbp * 16 + knr;
                    const int kch  = kb * 2 + kkc;
                    const uint32_t addr = koff + nrow * 128 +
                        ((kch ^ (nrow & 7)) << 4);
                    uint32_t bf[4];
                    ldsm_x4(bf, addr);
                    MMA_F16(sa[nbp * 2],     qf[kb], bf[0], bf[1]);
                    MMA_F16(sa[nbp * 2 + 1], qf[kb], bf[2], bf[3]);
                }
            }

            if (need_mask) {
                const int r0 = wlo + p, r1 = r0 + 8;
#pragma unroll
                for (int ni = 0; ni < 8; ni++) {
                    const int cgl = dcol + ni * 8 + 2 * q;
                    if (cgl     > r0) sa[ni][0] = -1e30f;
                    if (cgl + 1 > r0) sa[ni][1] = -1e30f;
                    if (cgl     > r1) sa[ni][2] = -1e30f;
                    if (cgl + 1 > r1) sa[ni][3] = -1e30f;
                }
            }

            // ---- softmax numerator (static shift = 0) fused with PV ----
            float lsum[4] = {0.f, 0.f, 0.f, 0.f};
#pragma unroll
            for (int kb = 0; kb < 4; kb++) {
                uint32_t pa[4];
                {
                    const int n0i = 2 * kb, n1i = 2 * kb + 1;
                    float e0 = fast_exp2(sa[n0i][0] * C2F);
                    float e1 = fast_exp2(sa[n0i][1] * C2F);
                    float e2 = fast_exp2(sa[n0i][2] * C2F);
                    float e3 = fast_exp2(sa[n0i][3] * C2F);
                    pa[0] = pack_h2(e0, e1);
                    pa[1] = pack_h2(e2, e3);
                    e0 = fast_exp2(sa[n1i][0] * C2F);
                    e1 = fast_exp2(sa[n1i][1] * C2F);
                    e2 = fast_exp2(sa[n1i][2] * C2F);
                    e3 = fast_exp2(sa[n1i][3] * C2F);
                    pa[2] = pack_h2(e0, e1);
                    pa[3] = pack_h2(e2, e3);
                }
                MMA_F16(lsum, pa, HONES, HONES);
                const int row = kb * 16 + brow;
#pragma unroll
                for (int nbp = 0; nbp < 4; nbp++) {
                    const int colh = nbp * 16 + bc8;
                    const uint32_t addr = voff + row * 128 +
                        ((((colh >> 3) ^ (row & 7)) << 4));
                    uint32_t bf[4];
                    ldsm_x4_t(bf, addr);
                    MMA_F16(o[nbp * 2],     pa, bf[0], bf[1]);
                    MMA_F16(o[nbp * 2 + 1], pa, bf[2], bf[3]);
                }
            }
            l0 += lsum[0];
            l1 += lsum[2];
        }
    }

    // ---- epilogue ----
    const float inv0 = 1.f / l0, inv1 = 1.f / l1;
    __half* Ob = Oh + ((size_t)(b * NN + qrow)) * DD + h * DHD;
#pragma unroll
    for (int ni = 0; ni < 8; ni++) {
        const int col = ni * 8 + 2 * q;
        *(uint32_t*)&Ob[(size_t)p * DD + col] =
            pack_h2(o[ni][0] * inv0, o[ni][1] * inv0);
        *(uint32_t*)&Ob[(size_t)(p + 8) * DD + col] =
            pack_h2(o[ni][2] * inv1, o[ni][3] * inv1);
    }
}

// ===========================================================================
extern "C" void kernel_launch(void* const* d_in, const int* in_sizes, int n_in,
                              void* d_out, int out_size)
{
    const float* x  = (const float*)d_in[0];
    const float* Wq = (const float*)d_in[1];
    const float* Wk = (const float*)d_in[2];
    const float* Wv = (const float*)d_in[3];
    const float* Wo = (const float*)d_in[4];
    const float* bo = (const float*)d_in[5];
    float* out = (float*)d_out;

    __half* ch;
    cudaGetSymbolAddress((void**)&ch, g_ch);

    cudaFuncSetAttribute(gemm_qkv, cudaFuncAttributeMaxDynamicSharedMemorySize, GH_SMEM);
    cudaFuncSetAttribute(gemm_wo,  cudaFuncAttributeMaxDynamicSharedMemorySize, GH_SMEM);
    cudaFuncSetAttribute(flash_h,  cudaFuncAttributeMaxDynamicSharedMemorySize, FL_SMEM);

    wprep<<<dim3(DD * DD / 256, 4), 256>>>(Wq, Wk, Wv, Wo);
    xprep<<<(MTOT * DD) / 1024, 256>>>(x);

    gemm_qkv<<<dim3(24, MTOT / 128), 256, GH_SMEM>>>();

    flash_h<<<dim3(16, HH, BB), 256, FL_SMEM>>>(ch);

    gemm_wo<<<dim3(DD / 128, MTOT / 128), 256, GH_SMEM>>>(bo, out);
}

// round 15
// speedup vs baseline: 1.0195x; 1.0195x over previous
#include <cuda_runtime.h>
#include <cuda_fp16.h>
#include <cstdint>
#include <math.h>

#define BB 4
#define NN 2048
#define DD 1024
#define HH 16
#define DHD 64
#define MTOT (BB*NN)   // 8192

// Scratch (device globals)
__device__ __half g_xh[MTOT * DD];
__device__ __half g_qh[MTOT * DD];   // Q pre-scaled by log2(e)/8
__device__ __half g_kh[MTOT * DD];
__device__ __half g_vh[MTOT * DD];
__device__ __half g_ch[MTOT * DD];
__device__ __half g_wh[4 * DD * DD];

#define C2F 0.18033688f   /* log2(e) / sqrt(64) */

__device__ __forceinline__ uint32_t smem_u32(const void* p) {
    uint32_t a;
    asm("{ .reg .u64 t; cvta.to.shared.u64 t, %1; cvt.u32.u64 %0, t; }" : "=r"(a) : "l"(p));
    return a;
}
__device__ __forceinline__ uint32_t pack_h2(float x, float y) {
    __half2 h = __floats2half2_rn(x, y);
    return *(uint32_t*)&h;
}
__device__ __forceinline__ uint32_t h2exp2(uint32_t x) {
    uint32_t y;
    asm("ex2.approx.f16x2 %0, %1;" : "=r"(y) : "r"(x));
    return y;
}
__device__ __forceinline__ void ldsm_x4(uint32_t* r, uint32_t addr) {
    asm volatile("ldmatrix.sync.aligned.m8n8.x4.shared.b16 {%0,%1,%2,%3}, [%4];"
                 : "=r"(r[0]), "=r"(r[1]), "=r"(r[2]), "=r"(r[3]) : "r"(addr));
}
__device__ __forceinline__ void ldsm_x4_t(uint32_t* r, uint32_t addr) {
    asm volatile("ldmatrix.sync.aligned.m8n8.x4.trans.shared.b16 {%0,%1,%2,%3}, [%4];"
                 : "=r"(r[0]), "=r"(r[1]), "=r"(r[2]), "=r"(r[3]) : "r"(addr));
}
#define MMA_F16(c, a, b0, b1)                                                 \
    asm volatile("mma.sync.aligned.m16n8k16.row.col.f32.f16.f16.f32 "         \
                 "{%0,%1,%2,%3},{%4,%5,%6,%7},{%8,%9},{%0,%1,%2,%3};"         \
                 : "+f"((c)[0]), "+f"((c)[1]), "+f"((c)[2]), "+f"((c)[3])     \
                 : "r"((a)[0]), "r"((a)[1]), "r"((a)[2]), "r"((a)[3]),        \
                   "r"(b0), "r"(b1))
#define CP_ASYNC16(dst, src)                                                  \
    asm volatile("cp.async.cg.shared.global [%0], [%1], 16;" :: "r"(dst), "l"(src))
#define CP_COMMIT()  asm volatile("cp.async.commit_group;")
#define CP_WAIT0()   asm volatile("cp.async.wait_group 0;")
#define CP_WAIT1()   asm volatile("cp.async.wait_group 1;")
#define HONES 0x3C003C00u   /* (1.0h, 1.0h) */

// ===========================================================================
// Prep kernels
// ===========================================================================
__global__ void wprep(const float* __restrict__ W0, const float* __restrict__ W1,
                      const float* __restrict__ W2, const float* __restrict__ W3)
{
    const float* S;
    switch (blockIdx.y) {
        case 0: S = W0; break;
        case 1: S = W1; break;
        case 2: S = W2; break;
        default: S = W3; break;
    }
    int idx = blockIdx.x * 256 + threadIdx.x;
    g_wh[(size_t)blockIdx.y * DD * DD + idx] = __float2half_rn(S[idx]);
}

__global__ void xprep(const float* __restrict__ x)
{
    size_t i = ((size_t)blockIdx.x * 256 + threadIdx.x) * 4;
    float4 v = *(const float4*)(x + i);
    uint2 u;
    u.x = pack_h2(v.x, v.y);
    u.y = pack_h2(v.z, v.w);
    *(uint2*)&g_xh[i] = u;
}

// ===========================================================================
// fp16 GEMM: 128x128 CTA tile, BK=64, 8 warps, 3-stage cp.async pipeline,
// B-fragment register double-buffering. Optional output scale on fp16 path.
// ===========================================================================
#define ASTR 72
#define BSTR 136
#define ABUF (128 * ASTR)
#define BBUF (64 * BSTR)
#define SBUF (ABUF + BBUF)
#define GH_SMEM (3 * SBUF * 2)        // 107520 bytes

__device__ __forceinline__
void gemm_body(const __half* __restrict__ Ah, const __half* __restrict__ Wh,
               const float* __restrict__ bias, float* __restrict__ Cf,
               __half* __restrict__ Ch, int m0, int n0, float oscale)
{
    extern __shared__ __align__(16) __half hsm[];
    const uint32_t smb = smem_u32(hsm);
    uint32_t asb[3], bsb[3];
#pragma unroll
    for (int s = 0; s < 3; s++) {
        asb[s] = smb + s * SBUF * 2;
        bsb[s] = asb[s] + ABUF * 2;
    }

    const int tid  = threadIdx.x;
    const int lane = tid & 31, wid = tid >> 5;
    const int wm = wid & 3, wn = wid >> 2;
    const int p = lane >> 2, q = lane & 3;

    auto cp_tile = [&](int k0, int s) {
#pragma unroll
        for (int i = 0; i < 4; i++) {
            const int j = tid + i * 256;
            const int row = j >> 3, c8 = j & 7;
            CP_ASYNC16(asb[s] + (row * ASTR + c8 * 8) * 2,
                       Ah + (size_t)(m0 + row) * DD + k0 + c8 * 8);
        }
#pragma unroll
        for (int i = 0; i < 4; i++) {
            const int j = tid + i * 256;
            const int row = j >> 4, cc = j & 15;
            CP_ASYNC16(bsb[s] + (row * BSTR + cc * 8) * 2,
                       Wh + (size_t)(k0 + row) * DD + n0 + cc * 8);
        }
    };

    float c[2][8][4];
#pragma unroll
    for (int mi = 0; mi < 2; mi++)
#pragma unroll
        for (int ni = 0; ni < 8; ni++)
#pragma unroll
            for (int e = 0; e < 4; e++) c[mi][ni][e] = 0.f;

    const int lrow  = lane & 15;
    const int lcolA = (lane >> 4) * 8;
    const int brow  = (lane & 7) + ((lane >> 3) & 1) * 8;
    const int bcol  = wn * 64 + ((lane >> 4) & 1) * 8;

    cp_tile(0, 0);  CP_COMMIT();
    cp_tile(64, 1); CP_COMMIT();

    uint32_t bf[2][4][4];

    for (int ks = 0; ks < 16; ks++) {
        const int s = ks % 3;
        if (ks == 15) { CP_WAIT0(); } else { CP_WAIT1(); }
        __syncthreads();
        if (ks + 2 < 16) {
            cp_tile((ks + 2) * 64, (ks + 2) % 3);
            CP_COMMIT();
        }

#pragma unroll
        for (int pr = 0; pr < 4; pr++)
            ldsm_x4_t(bf[0][pr], bsb[s] + (brow * BSTR + bcol + pr * 16) * 2);

#pragma unroll
        for (int kk = 0; kk < 4; kk++) {
            const int cur = kk & 1;
            if (kk < 3) {
#pragma unroll
                for (int pr = 0; pr < 4; pr++)
                    ldsm_x4_t(bf[cur ^ 1][pr], bsb[s] +
                              (((kk + 1) * 16 + brow) * BSTR + bcol + pr * 16) * 2);
            }
            uint32_t a[2][4];
#pragma unroll
            for (int mi = 0; mi < 2; mi++)
                ldsm_x4(a[mi], asb[s] +
                        ((wm * 32 + mi * 16 + lrow) * ASTR + kk * 16 + lcolA) * 2);
#pragma unroll
            for (int mi = 0; mi < 2; mi++)
#pragma unroll
                for (int pr = 0; pr < 4; pr++) {
                    MMA_F16(c[mi][2 * pr],     a[mi], bf[cur][pr][0], bf[cur][pr][1]);
                    MMA_F16(c[mi][2 * pr + 1], a[mi], bf[cur][pr][2], bf[cur][pr][3]);
                }
        }
    }

#pragma unroll
    for (int mi = 0; mi < 2; mi++) {
        const int r = m0 + wm * 32 + mi * 16 + p;
#pragma unroll
        for (int ni = 0; ni < 8; ni++) {
            const int col = n0 + wn * 64 + ni * 8 + 2 * q;
            if (Ch) {
                *(uint32_t*)&Ch[(size_t)r * DD + col] =
                    pack_h2(c[mi][ni][0] * oscale, c[mi][ni][1] * oscale);
                *(uint32_t*)&Ch[(size_t)(r + 8) * DD + col] =
                    pack_h2(c[mi][ni][2] * oscale, c[mi][ni][3] * oscale);
            } else {
                float2 v0 = make_float2(c[mi][ni][0], c[mi][ni][1]);
                float2 v1 = make_float2(c[mi][ni][2], c[mi][ni][3]);
                if (bias) {
                    float b0 = bias[col], b1 = bias[col + 1];
                    v0.x += b0; v0.y += b1;
                    v1.x += b0; v1.y += b1;
                }
                *(float2*)&Cf[(size_t)r * DD + col]       = v0;
                *(float2*)&Cf[(size_t)(r + 8) * DD + col] = v1;
            }
        }
    }
}

__global__ __launch_bounds__(256, 2)
void gemm_qkv()
{
    const int widx = blockIdx.x >> 3;
    const int n0 = (blockIdx.x & 7) * 128;
    __half* outp = (widx == 0) ? g_qh : (widx == 1) ? g_kh : g_vh;
    const float sc = (widx == 0) ? C2F : 1.0f;   // fold softmax scale into Q
    gemm_body(g_xh, g_wh + (size_t)widx * DD * DD, nullptr, nullptr, outp,
              blockIdx.y * 128, n0, sc);
}

__global__ __launch_bounds__(256, 2)
void gemm_wo(const float* __restrict__ bias, float* __restrict__ out)
{
    gemm_body(g_ch, g_wh + (size_t)3 * DD * DD, bias, out, nullptr,
              blockIdx.y * 128, blockIdx.x * 128, 1.0f);
}

// ===========================================================================
// fp16 causal flash attention, 128-row q-tiles, 256 threads (8 warps),
// paired q-tiles {i, 15-i} per CTA (equal work). 128-token KV tiles
// (2 x 64-chunk), 2-buffer cp.async, one barrier per 128 tokens.
// Static softmax shift (max := 0); Q pre-scaled by log2(e)/8 in gemm;
// exp via ex2.approx.f16x2 (pack then exp — MUFU count halved);
// row sums via ones-mma.
// Grid (8, HH, BB).
// ===========================================================================
#define KVTILE_B (128 * 64 * 2)       // 16384 B per K (or V) tile
#define FL_SMEM (2 * 2 * KVTILE_B)    // 65536 B

__global__ __launch_bounds__(256, 2)
void flash_h(__half* __restrict__ Oh)
{
    extern __shared__ __align__(16) __half fsm[];
    const uint32_t base = smem_u32(fsm);

    const int tid  = threadIdx.x;
    const int lane = tid & 31, w = tid >> 5;
    const int p = lane >> 2, q = lane & 3;
    const int h = blockIdx.y, b = blockIdx.z;
    const int pair = blockIdx.x;

    const __half* Kb = g_kh + ((size_t)b * NN) * DD + h * DHD;
    const __half* Vb = g_vh + ((size_t)b * NN) * DD + h * DHD;

    auto cp_kv = [&](int kv, int s) {
        const uint32_t kdst = base + s * 2 * KVTILE_B;
        const uint32_t vdst = kdst + KVTILE_B;
#pragma unroll
        for (int i = 0; i < 4; i++) {
            const int j = tid + i * 256;
            const int row = j >> 3, cc = j & 7;
            const uint32_t off = (row * 64 + ((cc ^ (row & 7)) * 8)) * 2;
            CP_ASYNC16(kdst + off, Kb + (size_t)(kv * 128 + row) * DD + cc * 8);
            CP_ASYNC16(vdst + off, Vb + (size_t)(kv * 128 + row) * DD + cc * 8);
        }
    };

    const int brow = (lane & 7) + ((lane >> 3) & 1) * 8;
    const int bc8  = ((lane >> 4) & 1) * 8;
    const int knr  = ((lane >> 4) & 1) * 8 + (lane & 7);
    const int kkc  = (lane >> 3) & 1;

    for (int half_i = 0; half_i < 2; half_i++) {
        const int t = half_i ? (15 - pair) : pair;
        const int qrow = t * 128 + w * 16;
        const __half* Qb = g_qh + ((size_t)(b * NN + qrow)) * DD + h * DHD;
        const int kmax = t;

        uint32_t qf[4][4];
#pragma unroll
        for (int kb = 0; kb < 4; kb++) {
            qf[kb][0] = *(const uint32_t*)(Qb + (size_t)p * DD + kb * 16 + 2 * q);
            qf[kb][1] = *(const uint32_t*)(Qb + (size_t)(p + 8) * DD + kb * 16 + 2 * q);
            qf[kb][2] = *(const uint32_t*)(Qb + (size_t)p * DD + kb * 16 + 2 * q + 8);
            qf[kb][3] = *(const uint32_t*)(Qb + (size_t)(p + 8) * DD + kb * 16 + 2 * q + 8);
        }

        float o[8][4];
#pragma unroll
        for (int ni = 0; ni < 8; ni++)
#pragma unroll
            for (int e = 0; e < 4; e++) o[ni][e] = 0.f;
        float l0 = 0.f, l1 = 0.f;

        __syncthreads();
        cp_kv(0, 0); CP_COMMIT();

        for (int kv = 0; kv <= kmax; kv++) {
            const int s = kv & 1;
            CP_WAIT0();
            __syncthreads();
            if (kv < kmax) {
                cp_kv(kv + 1, s ^ 1);
                CP_COMMIT();
            }
            const uint32_t kbase_s = base + s * 2 * KVTILE_B;
            const uint32_t vbase_s = kbase_s + KVTILE_B;

#pragma unroll
            for (int ch = 0; ch < 2; ch++) {
                const int dcol = kv * 128 + ch * 64 - t * 128;
                const int wlo = w * 16;
                if (dcol > wlo + 15) continue;
                const bool need_mask = (dcol + 63 > wlo);
                const uint32_t koff = kbase_s + ch * (64 * 64 * 2);
                const uint32_t voff = vbase_s + ch * (64 * 64 * 2);

                // ---- S' = (C2F*Q) @ K^T ----
                float sa[8][4];
#pragma unroll
                for (int ni = 0; ni < 8; ni++)
#pragma unroll
                    for (int e = 0; e < 4; e++) sa[ni][e] = 0.f;

#pragma unroll
                for (int kb = 0; kb < 4; kb++) {
#pragma unroll
                    for (int nbp = 0; nbp < 4; nbp++) {
                        const int nrow = nbp * 16 + knr;
                        const int kch  = kb * 2 + kkc;
                        const uint32_t addr = koff + nrow * 128 +
                            ((kch ^ (nrow & 7)) << 4);
                        uint32_t bf[4];
                        ldsm_x4(bf, addr);
                        MMA_F16(sa[nbp * 2],     qf[kb], bf[0], bf[1]);
                        MMA_F16(sa[nbp * 2 + 1], qf[kb], bf[2], bf[3]);
                    }
                }

                if (need_mask) {
                    const int r0 = wlo + p, r1 = r0 + 8;
#pragma unroll
                    for (int ni = 0; ni < 8; ni++) {
                        const int cgl = dcol + ni * 8 + 2 * q;
                        if (cgl     > r0) sa[ni][0] = -1e30f;
                        if (cgl + 1 > r0) sa[ni][1] = -1e30f;
                        if (cgl     > r1) sa[ni][2] = -1e30f;
                        if (cgl + 1 > r1) sa[ni][3] = -1e30f;
                    }
                }

                // ---- P = 2^(S') via f16x2 exp, fused with PV + ones-mma ----
                float lsum[4] = {0.f, 0.f, 0.f, 0.f};
#pragma unroll
                for (int kb = 0; kb < 4; kb++) {
                    uint32_t pa[4];
                    {
                        const int n0i = 2 * kb, n1i = 2 * kb + 1;
                        pa[0] = h2exp2(pack_h2(sa[n0i][0], sa[n0i][1]));
                        pa[1] = h2exp2(pack_h2(sa[n0i][2], sa[n0i][3]));
                        pa[2] = h2exp2(pack_h2(sa[n1i][0], sa[n1i][1]));
                        pa[3] = h2exp2(pack_h2(sa[n1i][2], sa[n1i][3]));
                    }
                    MMA_F16(lsum, pa, HONES, HONES);
                    const int row = kb * 16 + brow;
#pragma unroll
                    for (int nbp = 0; nbp < 4; nbp++) {
                        const int colh = nbp * 16 + bc8;
                        const uint32_t addr = voff + row * 128 +
                            ((((colh >> 3) ^ (row & 7)) << 4));
                        uint32_t bf[4];
                        ldsm_x4_t(bf, addr);
                        MMA_F16(o[nbp * 2],     pa, bf[0], bf[1]);
                        MMA_F16(o[nbp * 2 + 1], pa, bf[2], bf[3]);
                    }
                }
                l0 += lsum[0];
                l1 += lsum[2];
            }
        }

        // ---- epilogue ----
        const float inv0 = 1.f / l0, inv1 = 1.f / l1;
        __half* Ob = Oh + ((size_t)(b * NN + qrow)) * DD + h * DHD;
#pragma unroll
        for (int ni = 0; ni < 8; ni++) {
            const int col = ni * 8 + 2 * q;
            *(uint32_t*)&Ob[(size_t)p * DD + col] =
                pack_h2(o[ni][0] * inv0, o[ni][1] * inv0);
            *(uint32_t*)&Ob[(size_t)(p + 8) * DD + col] =
                pack_h2(o[ni][2] * inv1, o[ni][3] * inv1);
        }
    }
}

// ===========================================================================
extern "C" void kernel_launch(void* const* d_in, const int* in_sizes, int n_in,
                              void* d_out, int out_size)
{
    const float* x  = (const float*)d_in[0];
    const float* Wq = (const float*)d_in[1];
    const float* Wk = (const float*)d_in[2];
    const float* Wv = (const float*)d_in[3];
    const float* Wo = (const float*)d_in[4];
    const float* bo = (const float*)d_in[5];
    float* out = (float*)d_out;

    __half* ch;
    cudaGetSymbolAddress((void**)&ch, g_ch);

    cudaFuncSetAttribute(gemm_qkv, cudaFuncAttributeMaxDynamicSharedMemorySize, GH_SMEM);
    cudaFuncSetAttribute(gemm_wo,  cudaFuncAttributeMaxDynamicSharedMemorySize, GH_SMEM);
    cudaFuncSetAttribute(flash_h,  cudaFuncAttributeMaxDynamicSharedMemorySize, FL_SMEM);

    wprep<<<dim3(DD * DD / 256, 4), 256>>>(Wq, Wk, Wv, Wo);
    xprep<<<(MTOT * DD) / 1024, 256>>>(x);

    gemm_qkv<<<dim3(24, MTOT / 128), 256, GH_SMEM>>>();

    flash_h<<<dim3(8, HH, BB), 256, FL_SMEM>>>(ch);

    gemm_wo<<<dim3(DD / 128, MTOT / 128), 256, GH_SMEM>>>(bo, out);
}

// round 16
// speedup vs baseline: 1.0512x; 1.0311x over previous
#include <cuda_runtime.h>
#include <cuda_fp16.h>
#include <cstdint>
#include <math.h>

#define BB 4
#define NN 2048
#define DD 1024
#define HH 16
#define DHD 64
#define MTOT (BB*NN)   // 8192

// Scratch (device globals)
__device__ __half g_xh[MTOT * DD];
__device__ __half g_qh[MTOT * DD];   // Q pre-scaled by log2(e)/8
__device__ __half g_kh[MTOT * DD];
__device__ __half g_vh[MTOT * DD];
__device__ __half g_ch[MTOT * DD];
__device__ __half g_wh[4 * DD * DD];

#define C2F 0.18033688f   /* log2(e) / sqrt(64) */

__device__ __forceinline__ uint32_t smem_u32(const void* p) {
    uint32_t a;
    asm("{ .reg .u64 t; cvta.to.shared.u64 t, %1; cvt.u32.u64 %0, t; }" : "=r"(a) : "l"(p));
    return a;
}
__device__ __forceinline__ uint32_t pack_h2(float x, float y) {
    __half2 h = __floats2half2_rn(x, y);
    return *(uint32_t*)&h;
}
__device__ __forceinline__ uint32_t h2exp2(uint32_t x) {
    uint32_t y;
    asm("ex2.approx.f16x2 %0, %1;" : "=r"(y) : "r"(x));
    return y;
}
__device__ __forceinline__ void ldsm_x4(uint32_t* r, uint32_t addr) {
    asm volatile("ldmatrix.sync.aligned.m8n8.x4.shared.b16 {%0,%1,%2,%3}, [%4];"
                 : "=r"(r[0]), "=r"(r[1]), "=r"(r[2]), "=r"(r[3]) : "r"(addr));
}
__device__ __forceinline__ void ldsm_x4_t(uint32_t* r, uint32_t addr) {
    asm volatile("ldmatrix.sync.aligned.m8n8.x4.trans.shared.b16 {%0,%1,%2,%3}, [%4];"
                 : "=r"(r[0]), "=r"(r[1]), "=r"(r[2]), "=r"(r[3]) : "r"(addr));
}
#define MMA_F16(c, a, b0, b1)                                                 \
    asm volatile("mma.sync.aligned.m16n8k16.row.col.f32.f16.f16.f32 "         \
                 "{%0,%1,%2,%3},{%4,%5,%6,%7},{%8,%9},{%0,%1,%2,%3};"         \
                 : "+f"((c)[0]), "+f"((c)[1]), "+f"((c)[2]), "+f"((c)[3])     \
                 : "r"((a)[0]), "r"((a)[1]), "r"((a)[2]), "r"((a)[3]),        \
                   "r"(b0), "r"(b1))
#define CP_ASYNC16(dst, src)                                                  \
    asm volatile("cp.async.cg.shared.global [%0], [%1], 16;" :: "r"(dst), "l"(src))
#define CP_COMMIT()  asm volatile("cp.async.commit_group;")
#define CP_WAIT0()   asm volatile("cp.async.wait_group 0;")
#define CP_WAIT1()   asm volatile("cp.async.wait_group 1;")
#define HONES 0x3C003C00u   /* (1.0h, 1.0h) */

// ===========================================================================
// Fused prep: x fp32->fp16 (blocks 0..8191), W0..W3 fp32->fp16 (8192..12287)
// ===========================================================================
__global__ void prep_all(const float* __restrict__ x,
                         const float* __restrict__ W0, const float* __restrict__ W1,
                         const float* __restrict__ W2, const float* __restrict__ W3)
{
    const int bid = blockIdx.x;
    if (bid < 8192) {
        size_t i = ((size_t)bid * 256 + threadIdx.x) * 4;
        float4 v = *(const float4*)(x + i);
        uint2 u;
        u.x = pack_h2(v.x, v.y);
        u.y = pack_h2(v.z, v.w);
        *(uint2*)&g_xh[i] = u;
    } else {
        const int wb = bid - 8192;            // 0..4095
        const int widx = wb >> 10;            // 0..3
        const float* S;
        switch (widx) {
            case 0: S = W0; break;
            case 1: S = W1; break;
            case 2: S = W2; break;
            default: S = W3; break;
        }
        size_t i = ((size_t)(wb & 1023) * 256 + threadIdx.x) * 4;
        float4 v = *(const float4*)(S + i);
        uint2 u;
        u.x = pack_h2(v.x, v.y);
        u.y = pack_h2(v.z, v.w);
        *(uint2*)&g_wh[(size_t)widx * DD * DD + i] = u;
    }
}

// ===========================================================================
// fp16 GEMM: 128x128 CTA tile, BK=64, 8 warps, 3-stage cp.async pipeline,
// A-frag AND B-frag register double-buffering inside the stage.
// ===========================================================================
#define ASTR 72
#define BSTR 136
#define ABUF (128 * ASTR)
#define BBUF (64 * BSTR)
#define SBUF (ABUF + BBUF)
#define GH_SMEM (3 * SBUF * 2)        // 107520 bytes

__device__ __forceinline__
void gemm_body(const __half* __restrict__ Ah, const __half* __restrict__ Wh,
               const float* __restrict__ bias, float* __restrict__ Cf,
               __half* __restrict__ Ch, int m0, int n0, float oscale)
{
    extern __shared__ __align__(16) __half hsm[];
    const uint32_t smb = smem_u32(hsm);
    uint32_t asb[3], bsb[3];
#pragma unroll
    for (int s = 0; s < 3; s++) {
        asb[s] = smb + s * SBUF * 2;
        bsb[s] = asb[s] + ABUF * 2;
    }

    const int tid  = threadIdx.x;
    const int lane = tid & 31, wid = tid >> 5;
    const int wm = wid & 3, wn = wid >> 2;
    const int p = lane >> 2, q = lane & 3;

    auto cp_tile = [&](int k0, int s) {
#pragma unroll
        for (int i = 0; i < 4; i++) {
            const int j = tid + i * 256;
            const int row = j >> 3, c8 = j & 7;
            CP_ASYNC16(asb[s] + (row * ASTR + c8 * 8) * 2,
                       Ah + (size_t)(m0 + row) * DD + k0 + c8 * 8);
        }
#pragma unroll
        for (int i = 0; i < 4; i++) {
            const int j = tid + i * 256;
            const int row = j >> 4, cc = j & 15;
            CP_ASYNC16(bsb[s] + (row * BSTR + cc * 8) * 2,
                       Wh + (size_t)(k0 + row) * DD + n0 + cc * 8);
        }
    };

    float c[2][8][4];
#pragma unroll
    for (int mi = 0; mi < 2; mi++)
#pragma unroll
        for (int ni = 0; ni < 8; ni++)
#pragma unroll
            for (int e = 0; e < 4; e++) c[mi][ni][e] = 0.f;

    const int lrow  = lane & 15;
    const int lcolA = (lane >> 4) * 8;
    const int brow  = (lane & 7) + ((lane >> 3) & 1) * 8;
    const int bcol  = wn * 64 + ((lane >> 4) & 1) * 8;

    cp_tile(0, 0);  CP_COMMIT();
    cp_tile(64, 1); CP_COMMIT();

    uint32_t bf[2][4][4];   // double-buffered B fragments
    uint32_t af[2][2][4];   // double-buffered A fragments

    for (int ks = 0; ks < 16; ks++) {
        const int s = ks % 3;
        if (ks == 15) { CP_WAIT0(); } else { CP_WAIT1(); }
        __syncthreads();
        if (ks + 2 < 16) {
            cp_tile((ks + 2) * 64, (ks + 2) % 3);
            CP_COMMIT();
        }

        // preload frags for kk=0
#pragma unroll
        for (int pr = 0; pr < 4; pr++)
            ldsm_x4_t(bf[0][pr], bsb[s] + (brow * BSTR + bcol + pr * 16) * 2);
#pragma unroll
        for (int mi = 0; mi < 2; mi++)
            ldsm_x4(af[0][mi], asb[s] +
                    ((wm * 32 + mi * 16 + lrow) * ASTR + lcolA) * 2);

#pragma unroll
        for (int kk = 0; kk < 4; kk++) {
            const int cur = kk & 1;
            if (kk < 3) {
#pragma unroll
                for (int pr = 0; pr < 4; pr++)
                    ldsm_x4_t(bf[cur ^ 1][pr], bsb[s] +
                              (((kk + 1) * 16 + brow) * BSTR + bcol + pr * 16) * 2);
#pragma unroll
                for (int mi = 0; mi < 2; mi++)
                    ldsm_x4(af[cur ^ 1][mi], asb[s] +
                            ((wm * 32 + mi * 16 + lrow) * ASTR + (kk + 1) * 16 + lcolA) * 2);
            }
#pragma unroll
            for (int mi = 0; mi < 2; mi++)
#pragma unroll
                for (int pr = 0; pr < 4; pr++) {
                    MMA_F16(c[mi][2 * pr],     af[cur][mi], bf[cur][pr][0], bf[cur][pr][1]);
                    MMA_F16(c[mi][2 * pr + 1], af[cur][mi], bf[cur][pr][2], bf[cur][pr][3]);
                }
        }
    }

#pragma unroll
    for (int mi = 0; mi < 2; mi++) {
        const int r = m0 + wm * 32 + mi * 16 + p;
#pragma unroll
        for (int ni = 0; ni < 8; ni++) {
            const int col = n0 + wn * 64 + ni * 8 + 2 * q;
            if (Ch) {
                *(uint32_t*)&Ch[(size_t)r * DD + col] =
                    pack_h2(c[mi][ni][0] * oscale, c[mi][ni][1] * oscale);
                *(uint32_t*)&Ch[(size_t)(r + 8) * DD + col] =
                    pack_h2(c[mi][ni][2] * oscale, c[mi][ni][3] * oscale);
            } else {
                float2 v0 = make_float2(c[mi][ni][0], c[mi][ni][1]);
                float2 v1 = make_float2(c[mi][ni][2], c[mi][ni][3]);
                if (bias) {
                    float b0 = bias[col], b1 = bias[col + 1];
                    v0.x += b0; v0.y += b1;
                    v1.x += b0; v1.y += b1;
                }
                *(float2*)&Cf[(size_t)r * DD + col]       = v0;
                *(float2*)&Cf[(size_t)(r + 8) * DD + col] = v1;
            }
        }
    }
}

__global__ __launch_bounds__(256, 2)
void gemm_qkv()
{
    const int widx = blockIdx.x >> 3;
    const int n0 = (blockIdx.x & 7) * 128;
    __half* outp = (widx == 0) ? g_qh : (widx == 1) ? g_kh : g_vh;
    const float sc = (widx == 0) ? C2F : 1.0f;   // fold softmax scale into Q
    gemm_body(g_xh, g_wh + (size_t)widx * DD * DD, nullptr, nullptr, outp,
              blockIdx.y * 128, n0, sc);
}

__global__ __launch_bounds__(256, 2)
void gemm_wo(const float* __restrict__ bias, float* __restrict__ out)
{
    gemm_body(g_ch, g_wh + (size_t)3 * DD * DD, bias, out, nullptr,
              blockIdx.y * 128, blockIdx.x * 128, 1.0f);
}

// ===========================================================================
// fp16 causal flash attention (validated R15 design, unchanged):
// 128-row q-tiles paired {i, 15-i}, 8 warps, 128-token KV tiles (2x64 chunks),
// 2-buffer cp.async, one barrier per 128 tokens, static softmax shift,
// Q pre-scaled, f16x2 exp, row sums via ones-mma.
// Grid (8, HH, BB).
// ===========================================================================
#define KVTILE_B (128 * 64 * 2)       // 16384 B per K (or V) tile
#define FL_SMEM (2 * 2 * KVTILE_B)    // 65536 B

__global__ __launch_bounds__(256, 2)
void flash_h(__half* __restrict__ Oh)
{
    extern __shared__ __align__(16) __half fsm[];
    const uint32_t base = smem_u32(fsm);

    const int tid  = threadIdx.x;
    const int lane = tid & 31, w = tid >> 5;
    const int p = lane >> 2, q = lane & 3;
    const int h = blockIdx.y, b = blockIdx.z;
    const int pair = blockIdx.x;

    const __half* Kb = g_kh + ((size_t)b * NN) * DD + h * DHD;
    const __half* Vb = g_vh + ((size_t)b * NN) * DD + h * DHD;

    auto cp_kv = [&](int kv, int s) {
        const uint32_t kdst = base + s * 2 * KVTILE_B;
        const uint32_t vdst = kdst + KVTILE_B;
#pragma unroll
        for (int i = 0; i < 4; i++) {
            const int j = tid + i * 256;
            const int row = j >> 3, cc = j & 7;
            const uint32_t off = (row * 64 + ((cc ^ (row & 7)) * 8)) * 2;
            CP_ASYNC16(kdst + off, Kb + (size_t)(kv * 128 + row) * DD + cc * 8);
            CP_ASYNC16(vdst + off, Vb + (size_t)(kv * 128 + row) * DD + cc * 8);
        }
    };

    const int brow = (lane & 7) + ((lane >> 3) & 1) * 8;
    const int bc8  = ((lane >> 4) & 1) * 8;
    const int knr  = ((lane >> 4) & 1) * 8 + (lane & 7);
    const int kkc  = (lane >> 3) & 1;

    for (int half_i = 0; half_i < 2; half_i++) {
        const int t = half_i ? (15 - pair) : pair;
        const int qrow = t * 128 + w * 16;
        const __half* Qb = g_qh + ((size_t)(b * NN + qrow)) * DD + h * DHD;
        const int kmax = t;

        uint32_t qf[4][4];
#pragma unroll
        for (int kb = 0; kb < 4; kb++) {
            qf[kb][0] = *(const uint32_t*)(Qb + (size_t)p * DD + kb * 16 + 2 * q);
            qf[kb][1] = *(const uint32_t*)(Qb + (size_t)(p + 8) * DD + kb * 16 + 2 * q);
            qf[kb][2] = *(const uint32_t*)(Qb + (size_t)p * DD + kb * 16 + 2 * q + 8);
            qf[kb][3] = *(const uint32_t*)(Qb + (size_t)(p + 8) * DD + kb * 16 + 2 * q + 8);
        }

        float o[8][4];
#pragma unroll
        for (int ni = 0; ni < 8; ni++)
#pragma unroll
            for (int e = 0; e < 4; e++) o[ni][e] = 0.f;
        float l0 = 0.f, l1 = 0.f;

        __syncthreads();
        cp_kv(0, 0); CP_COMMIT();

        for (int kv = 0; kv <= kmax; kv++) {
            const int s = kv & 1;
            CP_WAIT0();
            __syncthreads();
            if (kv < kmax) {
                cp_kv(kv + 1, s ^ 1);
                CP_COMMIT();
            }
            const uint32_t kbase_s = base + s * 2 * KVTILE_B;
            const uint32_t vbase_s = kbase_s + KVTILE_B;

#pragma unroll
            for (int ch = 0; ch < 2; ch++) {
                const int dcol = kv * 128 + ch * 64 - t * 128;
                const int wlo = w * 16;
                if (dcol > wlo + 15) continue;
                const bool need_mask = (dcol + 63 > wlo);
                const uint32_t koff = kbase_s + ch * (64 * 64 * 2);
                const uint32_t voff = vbase_s + ch * (64 * 64 * 2);

                float sa[8][4];
#pragma unroll
                for (int ni = 0; ni < 8; ni++)
#pragma unroll
                    for (int e = 0; e < 4; e++) sa[ni][e] = 0.f;

#pragma unroll
                for (int kb = 0; kb < 4; kb++) {
#pragma unroll
                    for (int nbp = 0; nbp < 4; nbp++) {
                        const int nrow = nbp * 16 + knr;
                        const int kch  = kb * 2 + kkc;
                        const uint32_t addr = koff + nrow * 128 +
                            ((kch ^ (nrow & 7)) << 4);
                        uint32_t bf[4];
                        ldsm_x4(bf, addr);
                        MMA_F16(sa[nbp * 2],     qf[kb], bf[0], bf[1]);
                        MMA_F16(sa[nbp * 2 + 1], qf[kb], bf[2], bf[3]);
                    }
                }

                if (need_mask) {
                    const int r0 = wlo + p, r1 = r0 + 8;
#pragma unroll
                    for (int ni = 0; ni < 8; ni++) {
                        const int cgl = dcol + ni * 8 + 2 * q;
                        if (cgl     > r0) sa[ni][0] = -1e30f;
                        if (cgl + 1 > r0) sa[ni][1] = -1e30f;
                        if (cgl     > r1) sa[ni][2] = -1e30f;
                        if (cgl + 1 > r1) sa[ni][3] = -1e30f;
                    }
                }

                float lsum[4] = {0.f, 0.f, 0.f, 0.f};
#pragma unroll
                for (int kb = 0; kb < 4; kb++) {
                    uint32_t pa[4];
                    {
                        const int n0i = 2 * kb, n1i = 2 * kb + 1;
                        pa[0] = h2exp2(pack_h2(sa[n0i][0], sa[n0i][1]));
                        pa[1] = h2exp2(pack_h2(sa[n0i][2], sa[n0i][3]));
                        pa[2] = h2exp2(pack_h2(sa[n1i][0], sa[n1i][1]));
                        pa[3] = h2exp2(pack_h2(sa[n1i][2], sa[n1i][3]));
                    }
                    MMA_F16(lsum, pa, HONES, HONES);
                    const int row = kb * 16 + brow;
#pragma unroll
                    for (int nbp = 0; nbp < 4; nbp++) {
                        const int colh = nbp * 16 + bc8;
                        const uint32_t addr = voff + row * 128 +
                            ((((colh >> 3) ^ (row & 7)) << 4));
                        uint32_t bf[4];
                        ldsm_x4_t(bf, addr);
                        MMA_F16(o[nbp * 2],     pa, bf[0], bf[1]);
                        MMA_F16(o[nbp * 2 + 1], pa, bf[2], bf[3]);
                    }
                }
                l0 += lsum[0];
                l1 += lsum[2];
            }
        }

        const float inv0 = 1.f / l0, inv1 = 1.f / l1;
        __half* Ob = Oh + ((size_t)(b * NN + qrow)) * DD + h * DHD;
#pragma unroll
        for (int ni = 0; ni < 8; ni++) {
            const int col = ni * 8 + 2 * q;
            *(uint32_t*)&Ob[(size_t)p * DD + col] =
                pack_h2(o[ni][0] * inv0, o[ni][1] * inv0);
            *(uint32_t*)&Ob[(size_t)(p + 8) * DD + col] =
                pack_h2(o[ni][2] * inv1, o[ni][3] * inv1);
        }
    }
}

// ===========================================================================
extern "C" void kernel_launch(void* const* d_in, const int* in_sizes, int n_in,
                              void* d_out, int out_size)
{
    const float* x  = (const float*)d_in[0];
    const float* Wq = (const float*)d_in[1];
    const float* Wk = (const float*)d_in[2];
    const float* Wv = (const float*)d_in[3];
    const float* Wo = (const float*)d_in[4];
    const float* bo = (const float*)d_in[5];
    float* out = (float*)d_out;

    __half* ch;
    cudaGetSymbolAddress((void**)&ch, g_ch);

    cudaFuncSetAttribute(gemm_qkv, cudaFuncAttributeMaxDynamicSharedMemorySize, GH_SMEM);
    cudaFuncSetAttribute(gemm_wo,  cudaFuncAttributeMaxDynamicSharedMemorySize, GH_SMEM);
    cudaFuncSetAttribute(flash_h,  cudaFuncAttributeMaxDynamicSharedMemorySize, FL_SMEM);

    prep_all<<<12288, 256>>>(x, Wq, Wk, Wv, Wo);

    gemm_qkv<<<dim3(24, MTOT / 128), 256, GH_SMEM>>>();

    flash_h<<<dim3(8, HH, BB), 256, FL_SMEM>>>(ch);

    gemm_wo<<<dim3(DD / 128, MTOT / 128), 256, GH_SMEM>>>(bo, out);
}